// round 4
// baseline (speedup 1.0000x reference)
#include <cuda_runtime.h>
#include <cstdint>

// ---------------------------------------------------------------------------
// CapsNet forward, fused.
//  * routing never updates logits -> c uniform -> s[b,d,i] = mean_n dig[b,n,d]
//  * conv1 channel c = n*8+d; conv2 (kD=1) reduces over n per fixed d
//  * block = (d, batch-triple): 3 batches share every W2 stage (x3 amortize),
//    W2 double-buffered via cp.async (no exposed LDG latency).
//  * fp32 math via packed fma.rn.f32x2 (FFMA2), operands pre-paired.
// ---------------------------------------------------------------------------

typedef unsigned long long ull;

#define NTHR 576            // 18 warps: 3 groups x 6 row-warps
#define NGRP 3

// smem layout (floats)
#define OFF_X    0              // 3 x 784 images (reused as RED at end)
#define OFF_WA   2352           // 5184: W1, then W2[odd ci2]
#define OFF_WB   7536           // 5184: W2[even ci2]
#define OFF_C1   12720          // 3 x 16 x 804 conv1 out, ci-pair interleaved
#define C1_STRIDE 804
#define C1_SLAB  (16 * C1_STRIDE)
#define SMEM_FLOATS (12720 + 3 * C1_SLAB)    // 51312 -> 205.2 KB
#define SMEM_BYTES  (SMEM_FLOATS * 4)

__device__ float g_W1p[8][5184];    // [d][(tap*32+n)*2 + {0,1}] duplicated pair
__device__ float g_W2p[16][5184];   // [ci2][(tap*32+co)*2 + {even,odd}]
__device__ float g_partial[512 * 8 * 16];
__device__ float g_WbSum[16];
__device__ float g_WSum[160];

__device__ __forceinline__ ull ffma2(ull a, ull b, ull c) {
    ull d;
    asm("fma.rn.f32x2 %0, %1, %2, %3;" : "=l"(d) : "l"(a), "l"(b), "l"(c));
    return d;
}
__device__ __forceinline__ float lo32(ull v) { return __uint_as_float((unsigned)v); }
__device__ __forceinline__ float hi32(ull v) { return __uint_as_float((unsigned)(v >> 32)); }
__device__ __forceinline__ ull packf(unsigned lo, unsigned hi) {
    return ((ull)hi << 32) | lo;
}
__device__ __forceinline__ uint32_t smem_u32(const void* p) {
    return (uint32_t)__cvta_generic_to_shared(p);
}
__device__ __forceinline__ void cp_async16(uint32_t dst, const void* src) {
    asm volatile("cp.async.cg.shared.global [%0], [%1], 16;" :: "r"(dst), "l"(src));
}
__device__ __forceinline__ void cp_commit() {
    asm volatile("cp.async.commit_group;");
}
template <int N>
__device__ __forceinline__ void cp_wait() {
    asm volatile("cp.async.wait_group %0;" :: "n"(N));
}

// ---------------------------------------------------------------------------
__global__ void caps_prepW(const float* __restrict__ w1,
                           const float* __restrict__ w2) {
    int t = blockIdx.x * blockDim.x + threadIdx.x;
    if (t < 8 * 2592) {
        int d = t / 2592, i = t % 2592;
        int n = i / 81, tap = i % 81;
        float w = w1[(n * 8 + d) * 81 + tap];
        g_W1p[d][(tap * 32 + n) * 2 + 0] = w;
        g_W1p[d][(tap * 32 + n) * 2 + 1] = w;
    }
    if (t < 16 * 2592) {
        int c2 = t / 2592, i = t % 2592;
        int co = i / 81, tap = i % 81;
        g_W2p[c2][(tap * 32 + co) * 2 + 0] = w2[co * 2592 + (2 * c2) * 81 + tap];
        g_W2p[c2][(tap * 32 + co) * 2 + 1] = w2[co * 2592 + (2 * c2 + 1) * 81 + tap];
    }
}

__global__ void caps_prepS(const float* __restrict__ digWb,
                           const float* __restrict__ outw) {
    __shared__ float acc[256];
    int t = threadIdx.x;
    int e = t & 15, grp = t >> 4;
    float s = 0.f;
    for (int n = grp; n < 1152; n += 16) s += digWb[n * 16 + e];
    acc[t] = s;
    __syncthreads();
    if (t < 16) {
        float tot = 0.f;
        #pragma unroll
        for (int g = 0; g < 16; g++) tot += acc[g * 16 + t];
        g_WbSum[t] = tot;
    }
    if (t < 160) {
        int o = t / 16, k = t & 15;
        float w = 0.f;
        #pragma unroll
        for (int i = 0; i < 10; i++) w += outw[(o * 10 + i) * 16 + k];
        g_WSum[t] = w;
    }
}

// ---------------------------------------------------------------------------
// fused: grid (8 d, 171 batch-triples), 576 threads.
// warp w: group g = w/6 (batch), row-warp r = w%6.
// ---------------------------------------------------------------------------
__global__ void __launch_bounds__(NTHR, 1)
caps_fused(const float* __restrict__ gx,  const float* __restrict__ gb1,
           const float* __restrict__ gpb, const float* __restrict__ gdW)
{
    extern __shared__ float sm[];
    float* Xall = sm + OFF_X;
    float* WA   = sm + OFF_WA;
    float* WB   = sm + OFF_WB;
    float* C1a  = sm + OFF_C1;

    const int d    = blockIdx.x;
    const int bq   = blockIdx.y;
    const int tid  = threadIdx.x;
    const int lane = tid & 31;
    const int warp = tid >> 5;
    const int g    = warp / 6;         // batch group 0..2
    const int r    = warp % 6;         // row warp 0..5

    const int bb = min(bq * 3 + g, 511);   // clamped (dup writes identical)

    float* X  = Xall + g * 784;
    float* C1 = C1a  + g * C1_SLAB;

    // ---- stage: W1 -> WA (cp.async g0), W2[0] -> WB (g1), images (LDG) ----
    {
        const float4* ws = reinterpret_cast<const float4*>(g_W1p[d]);
        for (int i = tid; i < 1296; i += NTHR)
            cp_async16(smem_u32(WA + 4 * i), ws + i);
        cp_commit();
        const float4* w2s = reinterpret_cast<const float4*>(g_W2p[0]);
        for (int i = tid; i < 1296; i += NTHR)
            cp_async16(smem_u32(WB + 4 * i), w2s + i);
        cp_commit();
        // images: 3 x 196 float4
        float4* xd = reinterpret_cast<float4*>(Xall);
        for (int i = tid; i < 588; i += NTHR) {
            int gg = i / 196, idx = i % 196;
            int bsel = min(bq * 3 + gg, 511);
            xd[i] = reinterpret_cast<const float4*>(gx + bsel * 784)[idx];
        }
    }
    cp_wait<1>();        // W1 complete (W2[0] may still be in flight)
    __syncthreads();

    const float b1 = gb1[lane * 8 + d];

    // ---- conv1: 9x9 VALID, 28x28 -> 20x20, channel = lane ------------------
    for (int y = r; y < 20; y += 6) {
        ull accP[10];
        #pragma unroll
        for (int xp = 0; xp < 10; xp++) accP[xp] = 0ull;

        #pragma unroll 1
        for (int ky = 0; ky < 9; ky++) {
            const float* row = X + (y + ky) * 28;
            ull P[27];
            #pragma unroll
            for (int i = 0; i < 14; i++) P[2 * i] = *(const ull*)(row + 2 * i);
            #pragma unroll
            for (int i = 0; i < 13; i++)
                P[2 * i + 1] = packf((unsigned)(P[2 * i] >> 32),
                                     (unsigned)P[2 * i + 2]);
            #pragma unroll
            for (int kx = 0; kx < 9; kx++) {
                ull wp = *(const ull*)(WA + ((ky * 9 + kx) * 32 + lane) * 2);
                #pragma unroll
                for (int xp = 0; xp < 10; xp++)
                    accP[xp] = ffma2(P[2 * xp + kx], wp, accP[xp]);
            }
        }
        const int cbase = (lane >> 1) * C1_STRIDE + (lane & 1);
        #pragma unroll
        for (int xp = 0; xp < 10; xp++) {
            float v0 = fmaxf(lo32(accP[xp]) + b1, 0.f);
            float v1 = fmaxf(hi32(accP[xp]) + b1, 0.f);
            C1[cbase + (y * 20 + 2 * xp) * 2]     = v0;
            C1[cbase + (y * 20 + 2 * xp + 1) * 2] = v1;
        }
    }
    __syncthreads();     // conv1 done everywhere; WA free for W2[1]

    // ---- conv2: 32ci -> 32co, 9x9 stride 2 -> 6x6; double-buffered W2 ------
    const float pb = gpb[lane];
    ull acc2[6];
    #pragma unroll
    for (int x = 0; x < 6; x++) acc2[x] = 0ull;

    #pragma unroll 1
    for (int ci2 = 0; ci2 < 16; ci2++) {
        float* cur = (ci2 & 1) ? WA : WB;
        if (ci2 + 1 < 16) {
            float* nxt = (ci2 & 1) ? WB : WA;
            const float4* ws = reinterpret_cast<const float4*>(g_W2p[ci2 + 1]);
            for (int i = tid; i < 1296; i += NTHR)
                cp_async16(smem_u32(nxt + 4 * i), ws + i);
            cp_commit();
            cp_wait<1>();   // cur's group complete, next stays in flight
        } else {
            cp_wait<0>();
        }
        __syncthreads();

        const float* cb = C1 + ci2 * C1_STRIDE;
        #pragma unroll 1
        for (int ky = 0; ky < 9; ky++) {
            const float* rp = cb + (2 * r + ky) * 40;
            ull P[20];
            #pragma unroll
            for (int c4 = 0; c4 < 10; c4++) {
                ulonglong2 q = *(const ulonglong2*)(rp + c4 * 4);
                P[2 * c4]     = q.x;
                P[2 * c4 + 1] = q.y;
            }
            #pragma unroll
            for (int kx = 0; kx < 9; kx++) {
                ull wp = *(const ull*)(cur + ((ky * 9 + kx) * 32 + lane) * 2);
                #pragma unroll
                for (int x = 0; x < 6; x++)
                    acc2[x] = ffma2(P[2 * x + kx], wp, acc2[x]);
            }
        }
        __syncthreads();    // cur consumers done before it is overwritten
    }

    // ---- bias+relu -> u; partial contraction with dig_W --------------------
    float u[6];
    #pragma unroll
    for (int x = 0; x < 6; x++)
        u[x] = fmaxf(lo32(acc2[x]) + hi32(acc2[x]) + pb, 0.f);

    float part[16];
    #pragma unroll
    for (int e = 0; e < 16; e++) part[e] = 0.f;
    #pragma unroll
    for (int x = 0; x < 6; x++) {
        int n = lane * 36 + x * 6 + r;
        const float4* wv = reinterpret_cast<const float4*>(gdW + n * 128 + d * 16);
        #pragma unroll
        for (int q = 0; q < 4; q++) {
            float4 w4 = wv[q];
            part[q * 4 + 0] += u[x] * w4.x;
            part[q * 4 + 1] += u[x] * w4.y;
            part[q * 4 + 2] += u[x] * w4.z;
            part[q * 4 + 3] += u[x] * w4.w;
        }
    }
    #pragma unroll
    for (int off = 16; off; off >>= 1) {
        #pragma unroll
        for (int e = 0; e < 16; e++)
            part[e] += __shfl_xor_sync(0xffffffffu, part[e], off);
    }

    float* RED = X;           // X slab dead after conv1
    __syncthreads();
    if (lane == 0) {
        #pragma unroll
        for (int e = 0; e < 16; e++) RED[r * 16 + e] = part[e];
    }
    __syncthreads();
    if (r == 0 && lane < 16) {
        float s = 0.f;
        #pragma unroll
        for (int w = 0; w < 6; w++) s += RED[w * 16 + lane];
        g_partial[(bb * 8 + d) * 16 + lane] = s;
    }
}

// ---------------------------------------------------------------------------
__global__ void caps_final(const float* __restrict__ outb, float* __restrict__ out) {
    const int b = blockIdx.x;
    const int lane = threadIdx.x;

    float sb = 0.f;
    if (lane < 16) {
        float s = g_WbSum[lane];
        #pragma unroll
        for (int d = 0; d < 8; d++) s += g_partial[(b * 8 + d) * 16 + lane];
        sb = s * (1.0f / 1152.0f);
    }
    float sq = sb * sb, ab = fabsf(sb);
    #pragma unroll
    for (int off = 16; off; off >>= 1) {
        sq += __shfl_xor_sync(0xffffffffu, sq, off);
        ab += __shfl_xor_sync(0xffffffffu, ab, off);
    }
    float l2 = sqrtf(sq);
    float scale = l2 / ((1.f + l2) * ab);

    __shared__ float vsh[16];
    if (lane < 16) vsh[lane] = sb * scale;
    __syncwarp();

    float logit = -INFINITY;
    if (lane < 10) {
        float L = outb[lane];
        #pragma unroll
        for (int e = 0; e < 16; e++) L += vsh[e] * g_WSum[lane * 16 + e];
        logit = L;
    }
    float m = logit;
    #pragma unroll
    for (int off = 16; off; off >>= 1)
        m = fmaxf(m, __shfl_xor_sync(0xffffffffu, m, off));
    float ex = (lane < 10) ? expf(logit - m) : 0.f;
    float s = ex;
    #pragma unroll
    for (int off = 16; off; off >>= 1)
        s += __shfl_xor_sync(0xffffffffu, s, off);
    if (lane < 10) out[b * 10 + lane] = ex / s;
}

// ---------------------------------------------------------------------------
extern "C" void kernel_launch(void* const* d_in, const int* in_sizes, int n_in,
                              void* d_out, int out_size) {
    const float* x   = (const float*)d_in[0];
    const float* w1  = (const float*)d_in[1];
    const float* b1  = (const float*)d_in[2];
    const float* w2  = (const float*)d_in[3];
    const float* pb  = (const float*)d_in[4];
    const float* dW  = (const float*)d_in[5];
    const float* dWb = (const float*)d_in[6];
    const float* ow  = (const float*)d_in[7];
    const float* ob  = (const float*)d_in[8];
    float* out = (float*)d_out;

    (void)cudaFuncSetAttribute(caps_fused,
                               cudaFuncAttributeMaxDynamicSharedMemorySize,
                               SMEM_BYTES);

    caps_prepW<<<162, 256>>>(w1, w2);
    caps_fused<<<dim3(8, 171), NTHR, SMEM_BYTES>>>(x, b1, pb, dW);
    caps_prepS<<<1, 256>>>(dWb, ow);
    caps_final<<<512, 32>>>(ob, out);
}

// round 6
// speedup vs baseline: 1.1364x; 1.1364x over previous
#include <cuda_runtime.h>
#include <cstdint>

// ---------------------------------------------------------------------------
// CapsNet forward. tcgen05 is unavailable (harness targets plain sm_103), so
// tensor work uses legacy warp-level mma.sync m16n8k8 TF32 (sm_80+ feature),
// with the 3xTF32 (hi/lo split) scheme for fp32-grade accuracy (~2^-22).
//  * conv1: implicit GEMM, M=800 im2col rows (2 batches), N=32ch, K=88.
//  * conv2: implicit GEMM per (d, 2 batches): M=80 (72 real), N=32co,
//    K=81 taps x 32 ci; per-tap B tiles streamed via cp.async ring.
//  * routing reduces to a mean -> tiny dig_W partial epilogue.
// ---------------------------------------------------------------------------

#define NTHR 512

// smem float offsets
#define OFF_PB    16        // conv2 bias (32)
#define OFF_CB1   48        // conv1 bias for this d (32)
#define OFF_TAB   96        // 88 ints: conv1 tap->X offset
#define OFF_X     192       // 2 x 784 image (reused as RED)
#define OFF_W1F   1760      // 5632: conv1 B fragments (hi/lo)
#define OFF_BR    7392      // 4 x 2048: conv2 B-tile ring
#define OFF_C1    15584     // 2 x 13200: conv1 out, [pix*33 + ch]
#define OFF_CS    41984     // 4 x 2640: conv2 partials [cc][row*33+co]
#define OFF_RED   192       // overlay X
#define SMEM_FLOATS 52544
#define SMEM_BYTES  (SMEM_FLOATS * 4)

__device__ float g_W1f[8][5632];    // [d] conv1 W fragments [kc][nt][split][64]
__device__ float g_Btf[81][2048];   // [tap] conv2 W fragments [cc][nt][split][64]
__device__ float g_partial[512 * 8 * 16];
__device__ float g_WbSum[16];
__device__ float g_WSum[160];

__device__ __forceinline__ uint32_t smem_u32(const void* p) {
    return (uint32_t)__cvta_generic_to_shared(p);
}
__device__ __forceinline__ void cp_async16(uint32_t dst, const void* src) {
    asm volatile("cp.async.cg.shared.global [%0], [%1], 16;" :: "r"(dst), "l"(src));
}
__device__ __forceinline__ void cp_commit() { asm volatile("cp.async.commit_group;"); }
template <int N>
__device__ __forceinline__ void cp_wait() {
    asm volatile("cp.async.wait_group %0;" :: "n"(N));
}
__device__ __forceinline__ uint32_t cvt_tf32(float x) {
    uint32_t u;
    asm("cvt.rna.tf32.f32 %0, %1;" : "=r"(u) : "f"(x));
    return u;
}
__device__ __forceinline__ void mma8(float c[4],
                                     uint32_t a0, uint32_t a1, uint32_t a2, uint32_t a3,
                                     uint32_t b0, uint32_t b1) {
    asm volatile(
        "mma.sync.aligned.m16n8k8.row.col.f32.tf32.tf32.f32 "
        "{%0,%1,%2,%3}, {%4,%5,%6,%7}, {%8,%9}, {%0,%1,%2,%3};"
        : "+f"(c[0]), "+f"(c[1]), "+f"(c[2]), "+f"(c[3])
        : "r"(a0), "r"(a1), "r"(a2), "r"(a3), "r"(b0), "r"(b1));
}

// ---------------------------------------------------------------------------
// prepW: weight fragments, tf32 hi/lo, fragment-ordered for direct LDS.64.
// layout r = kcc*512 + nt*128 + split*64 + lane*2 + reg
// ---------------------------------------------------------------------------
__global__ void caps_prepW(const float* __restrict__ w1,
                           const float* __restrict__ w2) {
    int t = blockIdx.x * blockDim.x + threadIdx.x;
    if (t < 8 * 5632) {
        int d = t / 5632, r = t % 5632;
        int reg = r & 1, lane = (r >> 1) & 31, s2 = (r >> 6) & 1;
        int nt = (r >> 7) & 3, kc = r >> 9;
        int g = lane >> 2, q = lane & 3;
        int k = kc * 8 + q + reg * 4;
        int co = nt * 8 + g;
        float v = (k < 81) ? w1[(co * 8 + d) * 81 + k] : 0.f;
        uint32_t hi = cvt_tf32(v);
        uint32_t out = s2 ? cvt_tf32(v - __uint_as_float(hi)) : hi;
        g_W1f[d][r] = __uint_as_float(out);
    }
    if (t < 81 * 2048) {
        int tap = t / 2048, r = t % 2048;
        int reg = r & 1, lane = (r >> 1) & 31, s2 = (r >> 6) & 1;
        int nt = (r >> 7) & 3, cc = r >> 9;
        int g = lane >> 2, q = lane & 3;
        int ci = cc * 8 + q + reg * 4;
        int co = nt * 8 + g;
        float v = w2[(co * 32 + ci) * 81 + tap];
        uint32_t hi = cvt_tf32(v);
        uint32_t out = s2 ? cvt_tf32(v - __uint_as_float(hi)) : hi;
        g_Btf[tap][r] = __uint_as_float(out);
    }
}

__global__ void caps_prepS(const float* __restrict__ digWb,
                           const float* __restrict__ outw) {
    __shared__ float acc[256];
    int t = threadIdx.x;
    int e = t & 15, grp = t >> 4;
    float s = 0.f;
    for (int n = grp; n < 1152; n += 16) s += digWb[n * 16 + e];
    acc[t] = s;
    __syncthreads();
    if (t < 16) {
        float tot = 0.f;
        #pragma unroll
        for (int g = 0; g < 16; g++) tot += acc[g * 16 + t];
        g_WbSum[t] = tot;
    }
    if (t < 160) {
        int o = t / 16, k = t & 15;
        float w = 0.f;
        #pragma unroll
        for (int i = 0; i < 10; i++) w += outw[(o * 10 + i) * 16 + k];
        g_WSum[t] = w;
    }
}

// ---------------------------------------------------------------------------
// fused: grid (8 d, 256 batch-pairs), 512 threads (16 warps).
// ---------------------------------------------------------------------------
__global__ void __launch_bounds__(NTHR, 1)
caps_fused(const float* __restrict__ gx,  const float* __restrict__ gb1,
           const float* __restrict__ gpb, const float* __restrict__ gdW)
{
    extern __shared__ float sm[];
    int* smi = (int*)sm;
    const int d    = blockIdx.x;
    const int bq   = blockIdx.y;
    const int tid  = threadIdx.x;
    const int lane = tid & 31;
    const int warp = tid >> 5;
    const int g4   = lane >> 2;
    const int q4   = lane & 3;

    float* Xs  = sm + OFF_X;
    float* C1s = sm + OFF_C1;

    // ---- prologue staging ---------------------------------------------------
    for (int i = tid; i < 1408; i += NTHR)
        cp_async16(smem_u32(sm + OFF_W1F) + i * 16, (const char*)g_W1f[d] + i * 16);
    cp_commit();                                                // g0: W1f
    cp_async16(smem_u32(sm + OFF_BR) + tid * 16, (const char*)g_Btf[0] + tid * 16);
    cp_commit();                                                // g1: B0
    cp_async16(smem_u32(sm + OFF_BR + 2048) + tid * 16, (const char*)g_Btf[1] + tid * 16);
    cp_commit();                                                // g2: B1
    {
        float4* xd = (float4*)Xs;
        const float4* xsrc = (const float4*)(gx + (size_t)bq * 2 * 784);
        for (int i = tid; i < 392; i += NTHR) xd[i] = xsrc[i];
    }
    if (tid < 32) { sm[OFF_PB + tid] = gpb[tid]; sm[OFF_CB1 + tid] = gb1[tid * 8 + d]; }
    if (tid < 88) { int k = (tid < 81) ? tid : 80; smi[OFF_TAB + tid] = (k / 9) * 28 + (k % 9); }
    cp_wait<2>();                 // W1f done; B0/B1 may be in flight
    __syncthreads();

    // ---- conv1 via MMA: M=800, N=32, K=88 (two passes of 2 m-tiles) ---------
    {
        float* W1s = sm + OFF_W1F;
        #pragma unroll 1
        for (int pass = 0; pass < 2; pass++) {
            int mis[2] = { warp + 32 * pass, warp + 32 * pass + 16 };
            bool MV[2] = { mis[0] < 50, mis[1] < 50 };
            int XA[2], XB[2], PA[2], PB2[2];
            #pragma unroll
            for (int s = 0; s < 2; s++) {
                int mi = MV[s] ? mis[s] : 0;
                int r0 = mi * 16 + g4, r1 = r0 + 8;
                int gb = r0 / 400;
                int px0 = r0 - gb * 400, px1 = r1 - gb * 400;
                XA[s]  = gb * 784 + (px0 / 20) * 28 + px0 % 20;
                XB[s]  = gb * 784 + (px1 / 20) * 28 + px1 % 20;
                PA[s]  = gb * 13200 + px0 * 33;
                PB2[s] = gb * 13200 + px1 * 33;
            }
            float acc[2][4][4] = {};
            #pragma unroll
            for (int kc = 0; kc < 11; kc++) {
                int ta0 = smi[OFF_TAB + kc * 8 + q4];
                int ta1 = smi[OFF_TAB + kc * 8 + q4 + 4];
                uint32_t bh[4][2], bl[4][2];
                #pragma unroll
                for (int nt = 0; nt < 4; nt++) {
                    float2 h = *(const float2*)(W1s + kc * 512 + nt * 128 + lane * 2);
                    float2 l = *(const float2*)(W1s + kc * 512 + nt * 128 + 64 + lane * 2);
                    bh[nt][0] = __float_as_uint(h.x); bh[nt][1] = __float_as_uint(h.y);
                    bl[nt][0] = __float_as_uint(l.x); bl[nt][1] = __float_as_uint(l.y);
                }
                #pragma unroll
                for (int s = 0; s < 2; s++) if (MV[s]) {
                    float a0f = Xs[XA[s] + ta0], a1f = Xs[XB[s] + ta0];
                    float a2f = Xs[XA[s] + ta1], a3f = Xs[XB[s] + ta1];
                    uint32_t ah0 = cvt_tf32(a0f), ah1 = cvt_tf32(a1f);
                    uint32_t ah2 = cvt_tf32(a2f), ah3 = cvt_tf32(a3f);
                    uint32_t al0 = cvt_tf32(a0f - __uint_as_float(ah0));
                    uint32_t al1 = cvt_tf32(a1f - __uint_as_float(ah1));
                    uint32_t al2 = cvt_tf32(a2f - __uint_as_float(ah2));
                    uint32_t al3 = cvt_tf32(a3f - __uint_as_float(ah3));
                    #pragma unroll
                    for (int nt = 0; nt < 4; nt++) {
                        mma8(acc[s][nt], ah0, ah1, ah2, ah3, bh[nt][0], bh[nt][1]);
                        mma8(acc[s][nt], al0, al1, al2, al3, bh[nt][0], bh[nt][1]);
                        mma8(acc[s][nt], ah0, ah1, ah2, ah3, bl[nt][0], bl[nt][1]);
                    }
                }
            }
            #pragma unroll
            for (int s = 0; s < 2; s++) if (MV[s]) {
                #pragma unroll
                for (int nt = 0; nt < 4; nt++) {
                    int co = nt * 8 + 2 * q4;
                    float b0 = sm[OFF_CB1 + co], b1v = sm[OFF_CB1 + co + 1];
                    C1s[PA[s]  + co]     = fmaxf(acc[s][nt][0] + b0,  0.f);
                    C1s[PA[s]  + co + 1] = fmaxf(acc[s][nt][1] + b1v, 0.f);
                    C1s[PB2[s] + co]     = fmaxf(acc[s][nt][2] + b0,  0.f);
                    C1s[PB2[s] + co + 1] = fmaxf(acc[s][nt][3] + b1v, 0.f);
                }
            }
        }
    }
    __syncthreads();

    // ---- conv2 via MMA: M=80(72), N=32, K=81x32; 8 active warps -------------
    const int mh = warp >> 2, cc = warp & 3;
    const bool act = warp < 8;
    const int nmt2 = (mh == 0) ? 3 : 2;
    int Q0[3], Q1[3];
    if (act) {
        #pragma unroll
        for (int j = 0; j < 3; j++) {
            int mt = (mh ? 3 : 0) + j;
            int r0 = min(mt * 16 + g4, 71);
            int r1 = min(mt * 16 + g4 + 8, 71);
            int gA = r0 / 36, pxA = r0 - gA * 36, ya = pxA / 6, xa = pxA % 6;
            int gB = r1 / 36, pxB = r1 - gB * 36, yb = pxB / 6, xb = pxB % 6;
            Q0[j] = gA * 13200 + (2 * ya * 20 + 2 * xa) * 33 + cc * 8 + q4;
            Q1[j] = gB * 13200 + (2 * yb * 20 + 2 * xb) * 33 + cc * 8 + q4;
        }
    }
    float c2[3][4][4] = {};
    int toff = 0, kxc = 0;

    #pragma unroll 1
    for (int t = 0; t < 81; t++) {
        if (t + 2 < 81)
            cp_async16(smem_u32(sm + OFF_BR + ((t + 2) & 3) * 2048) + tid * 16,
                       (const char*)g_Btf[t + 2] + tid * 16);
        cp_commit();
        cp_wait<2>();          // B[t] complete
        __syncthreads();

        if (act) {
            const float* Bs = sm + OFF_BR + (t & 3) * 2048 + cc * 512;
            uint32_t bh[4][2], bl[4][2];
            #pragma unroll
            for (int nt = 0; nt < 4; nt++) {
                float2 h = *(const float2*)(Bs + nt * 128 + lane * 2);
                float2 l = *(const float2*)(Bs + nt * 128 + 64 + lane * 2);
                bh[nt][0] = __float_as_uint(h.x); bh[nt][1] = __float_as_uint(h.y);
                bl[nt][0] = __float_as_uint(l.x); bl[nt][1] = __float_as_uint(l.y);
            }
            #pragma unroll
            for (int j = 0; j < 3; j++) if (j < nmt2) {
                float a0f = C1s[Q0[j] + toff],     a1f = C1s[Q1[j] + toff];
                float a2f = C1s[Q0[j] + toff + 4], a3f = C1s[Q1[j] + toff + 4];
                uint32_t ah0 = cvt_tf32(a0f), ah1 = cvt_tf32(a1f);
                uint32_t ah2 = cvt_tf32(a2f), ah3 = cvt_tf32(a3f);
                uint32_t al0 = cvt_tf32(a0f - __uint_as_float(ah0));
                uint32_t al1 = cvt_tf32(a1f - __uint_as_float(ah1));
                uint32_t al2 = cvt_tf32(a2f - __uint_as_float(ah2));
                uint32_t al3 = cvt_tf32(a3f - __uint_as_float(ah3));
                #pragma unroll
                for (int nt = 0; nt < 4; nt++) {
                    mma8(c2[j][nt], ah0, ah1, ah2, ah3, bh[nt][0], bh[nt][1]);
                    mma8(c2[j][nt], al0, al1, al2, al3, bh[nt][0], bh[nt][1]);
                    mma8(c2[j][nt], ah0, ah1, ah2, ah3, bl[nt][0], bl[nt][1]);
                }
            }
            kxc++;
            if (kxc == 9) { kxc = 0; toff += 396; } else toff += 33;
        }
    }

    // ---- reduce partials over cc, then dig_W epilogue ------------------------
    if (act) {
        float* CS = sm + OFF_CS + cc * 2640;
        #pragma unroll
        for (int j = 0; j < 3; j++) if (j < nmt2) {
            int mt = (mh ? 3 : 0) + j;
            int r0 = mt * 16 + g4, r1 = r0 + 8;
            #pragma unroll
            for (int nt = 0; nt < 4; nt++) {
                int co = nt * 8 + 2 * q4;
                CS[r0 * 33 + co]     = c2[j][nt][0];
                CS[r0 * 33 + co + 1] = c2[j][nt][1];
                CS[r1 * 33 + co]     = c2[j][nt][2];
                CS[r1 * 33 + co + 1] = c2[j][nt][3];
            }
        }
    }
    __syncthreads();

    float* RED = sm + OFF_RED;     // X region (dead)
    if (tid < 72) {
        const int row = tid;
        const int gb = row / 36, px = row - gb * 36;
        const int y = px / 6, x = px - 6 * y;
        float part[16];
        #pragma unroll
        for (int e = 0; e < 16; e++) part[e] = 0.f;
        #pragma unroll 4
        for (int c = 0; c < 32; c++) {
            float u = sm[OFF_CS + row * 33 + c]
                    + sm[OFF_CS + 2640 + row * 33 + c]
                    + sm[OFF_CS + 5280 + row * 33 + c]
                    + sm[OFF_CS + 7920 + row * 33 + c]
                    + sm[OFF_PB + c];
            u = fmaxf(u, 0.f);
            const int n = c * 36 + x * 6 + y;
            const float4* wv = (const float4*)(gdW + n * 128 + d * 16);
            #pragma unroll
            for (int q = 0; q < 4; q++) {
                float4 w4 = wv[q];
                part[q * 4 + 0] += u * w4.x;
                part[q * 4 + 1] += u * w4.y;
                part[q * 4 + 2] += u * w4.z;
                part[q * 4 + 3] += u * w4.w;
            }
        }
        #pragma unroll
        for (int e = 0; e < 16; e++) RED[row * 16 + e] = part[e];
    }
    __syncthreads();
    if (tid < 32) {
        const int gb = tid >> 4, e = tid & 15;
        float s = 0.f;
        #pragma unroll
        for (int p = 0; p < 36; p++) s += RED[(gb * 36 + p) * 16 + e];
        g_partial[((bq * 2 + gb) * 8 + d) * 16 + e] = s;
    }
}

// ---------------------------------------------------------------------------
__global__ void caps_final(const float* __restrict__ outb, float* __restrict__ out) {
    const int b = blockIdx.x;
    const int lane = threadIdx.x;

    float sb = 0.f;
    if (lane < 16) {
        float s = g_WbSum[lane];
        #pragma unroll
        for (int d = 0; d < 8; d++) s += g_partial[(b * 8 + d) * 16 + lane];
        sb = s * (1.0f / 1152.0f);
    }
    float sq = sb * sb, ab = fabsf(sb);
    #pragma unroll
    for (int off = 16; off; off >>= 1) {
        sq += __shfl_xor_sync(0xffffffffu, sq, off);
        ab += __shfl_xor_sync(0xffffffffu, ab, off);
    }
    float l2 = sqrtf(sq);
    float scale = l2 / ((1.f + l2) * ab);

    __shared__ float vsh[16];
    if (lane < 16) vsh[lane] = sb * scale;
    __syncwarp();

    float logit = -INFINITY;
    if (lane < 10) {
        float L = outb[lane];
        #pragma unroll
        for (int e = 0; e < 16; e++) L += vsh[e] * g_WSum[lane * 16 + e];
        logit = L;
    }
    float m = logit;
    #pragma unroll
    for (int off = 16; off; off >>= 1)
        m = fmaxf(m, __shfl_xor_sync(0xffffffffu, m, off));
    float ex = (lane < 10) ? expf(logit - m) : 0.f;
    float s = ex;
    #pragma unroll
    for (int off = 16; off; off >>= 1)
        s += __shfl_xor_sync(0xffffffffu, s, off);
    if (lane < 10) out[b * 10 + lane] = ex / s;
}

// ---------------------------------------------------------------------------
extern "C" void kernel_launch(void* const* d_in, const int* in_sizes, int n_in,
                              void* d_out, int out_size) {
    const float* x   = (const float*)d_in[0];
    const float* w1  = (const float*)d_in[1];
    const float* b1  = (const float*)d_in[2];
    const float* w2  = (const float*)d_in[3];
    const float* pb  = (const float*)d_in[4];
    const float* dW  = (const float*)d_in[5];
    const float* dWb = (const float*)d_in[6];
    const float* ow  = (const float*)d_in[7];
    const float* ob  = (const float*)d_in[8];
    float* out = (float*)d_out;

    (void)cudaFuncSetAttribute(caps_fused,
                               cudaFuncAttributeMaxDynamicSharedMemorySize,
                               SMEM_BYTES);

    caps_prepW<<<648, 256>>>(w1, w2);
    caps_fused<<<dim3(8, 256), NTHR, SMEM_BYTES>>>(x, b1, pb, dW);
    caps_prepS<<<1, 256>>>(dWb, ow);
    caps_final<<<512, 32>>>(ob, out);
}